// round 5
// baseline (speedup 1.0000x reference)
#include <cuda_runtime.h>

#define NCAT 20
#define NNUM 20
#define EMBD 32
#define HID  128
#define NMOD 50
#define TILE 64            // 8 warps * 8 rows
#define NTHR 256

typedef unsigned long long u64;

// ---------------- f32x2 helpers (Blackwell packed fp32) ----------------
__device__ __forceinline__ u64 pk2(float lo, float hi) {
    u64 r; asm("mov.b64 %0,{%1,%2};" : "=l"(r) : "f"(lo), "f"(hi)); return r;
}
__device__ __forceinline__ float2 upk2(u64 v) {
    float2 f; asm("mov.b64 {%0,%1},%2;" : "=f"(f.x), "=f"(f.y) : "l"(v)); return f;
}
__device__ __forceinline__ u64 dup2(float a) {
    u64 r; asm("mov.b64 %0,{%1,%1};" : "=l"(r) : "f"(a)); return r;
}
__device__ __forceinline__ u64 fma2(u64 a, u64 b, u64 c) {
    u64 d; asm("fma.rn.f32x2 %0,%1,%2,%3;" : "=l"(d) : "l"(a), "l"(b), "l"(c)); return d;
}
__device__ __forceinline__ u64 add2(u64 a, u64 b) {
    u64 d; asm("add.rn.f32x2 %0,%1,%2;" : "=l"(d) : "l"(a), "l"(b)); return d;
}
__device__ __forceinline__ u64 mul2(u64 a, u64 b) {
    u64 d; asm("mul.rn.f32x2 %0,%1,%2;" : "=l"(d) : "l"(a), "l"(b)); return d;
}
// smem u2-index swizzle: spreads transposed stores across banks
__device__ __forceinline__ int swz(int i) { return i ^ ((i >> 3) & 7); }

// ---------------- device scratch ----------------
__device__ float g_Tcat[NCAT * NMOD * HID];
__device__ float g_A[3 * HID * HID];
__device__ float g_vnum[NNUM * HID];
__device__ float g_base[HID];
__device__ float g_d[3 * HID];

// ---------------- single merged precompute kernel ----------------
__global__ void pre_all_kernel(const float* __restrict__ emb,
                               const float* __restrict__ W_num, const float* __restrict__ b_num,
                               const float* __restrict__ W_in,  const float* __restrict__ b_in,
                               const float* __restrict__ W1,    const float* __restrict__ b1,
                               const float* __restrict__ W2,    const float* __restrict__ b2,
                               const float* __restrict__ ln_g,  const float* __restrict__ ln_b,
                               const float* __restrict__ W_out, const float* __restrict__ b_out) {
    const int b = blockIdx.x;
    const int j = threadIdx.x;
    if (b < NCAT * NMOD) {                       // --- Tcat fold ---
        int fc = b, f = fc / NMOD;
        const float* e = emb + fc * EMBD;
        float s = 0.f;
#pragma unroll
        for (int k = 0; k < EMBD; k++)
            s += e[k] * W_in[(f * EMBD + k) * HID + j];
        g_Tcat[fc * HID + j] = s;
    } else if (b < NCAT * NMOD + 3 * HID) {      // --- A matrices ---
        int bx = b - NCAT * NMOD;
        int s = bx >> 7, k = bx & 127;
        float v;
        if (s == 2) {
            v = ln_g[HID + k] * W_out[k * HID + j];
        } else {
            const float* w1 = W1 + s * HID * 2 * HID + k * 2 * HID;
            const float* w2 = W2 + s * 2 * HID * HID;
            float acc = 0.f;
            for (int m = 0; m < 2 * HID; m++) acc += w1[m] * w2[m * HID + j];
            v = (s == 1) ? ln_g[k] * acc : acc;
        }
        g_A[bx * HID + j] = v;
    } else {                                      // --- vectors ---
        for (int f = 0; f < NNUM; f++) {
            float s = 0.f;
#pragma unroll
            for (int k = 0; k < EMBD; k++)
                s += W_num[f * EMBD + k] * W_in[((NCAT + f) * EMBD + k) * HID + j];
            g_vnum[f * HID + j] = s;
        }
        float bb = b_in[j];
        for (int f = 0; f < NNUM; f++)
#pragma unroll
            for (int k = 0; k < EMBD; k++)
                bb += b_num[f * EMBD + k] * W_in[((NCAT + f) * EMBD + k) * HID + j];
        g_base[j] = bb;
        float d1 = b2[j];
        for (int m = 0; m < 2 * HID; m++) d1 += b1[m] * W2[m * HID + j];
        g_d[j] = d1;
        __shared__ float u[2 * HID];
        for (int m = j; m < 2 * HID; m += HID) {
            float s = 0.f;
            for (int k = 0; k < HID; k++)
                s += ln_b[k] * W1[HID * 2 * HID + k * 2 * HID + m];
            u[m] = s;
        }
        __syncthreads();
        float d2 = b2[HID + j];
        for (int m = 0; m < 2 * HID; m++)
            d2 += (u[m] + b1[2 * HID + m]) * W2[2 * HID * HID + m * HID + j];
        g_d[HID + j] = d2;
        float d3 = b_out[j];
        for (int k = 0; k < HID; k++) d3 += ln_b[HID + k] * W_out[k * HID + j];
        g_d[2 * HID + j] = d3;
    }
}

// ---------------- main fused kernel ----------------
// smem: A (3*128*128 f = 192KB) + per-warp htw (128 k * 2 ulonglong2, swizzled) = 4KB*8
#define SM_HT     (3 * HID * HID)                 // float offset 49152
#define SM_TOTALF (SM_HT + 8 * HID * 8)           // + 8192 floats -> 229376 B

__global__ __launch_bounds__(NTHR, 1)
void main_kernel(const float* __restrict__ x, float* __restrict__ out,
                 int nrows, int ntiles) {
    extern __shared__ float sm[];
    const int t = threadIdx.x;
    const int l = t & 31;          // lane: cols 4l..4l+3
    const int w = t >> 5;          // warp: rows 8w..8w+7 of tile

    ulonglong2* htw = (ulonglong2*)(sm + SM_HT) + w * 256;   // 256 u2 per warp

    // load folded matrices once per CTA
    {
        const float4* src = (const float4*)g_A;
        float4* dst = (float4*)sm;
        for (int i = t; i < 3 * HID * HID / 4; i += NTHR) dst[i] = src[i];
    }

    // per-thread constants
    const u64 bp0 = ((const u64*)g_base)[2 * l];
    const u64 bp1 = ((const u64*)g_base)[2 * l + 1];
    const float4 dv0 = ((const float4*)g_d)[l];
    const float4 dv1 = ((const float4*)g_d)[32 + l];
    const float4 dv2 = ((const float4*)g_d)[64 + l];
    const u64 inv2 = dup2(1.f / HID);

    __syncthreads();   // only CTA-wide barrier

    const ulonglong2* Tcat2 = (const ulonglong2*)g_Tcat;
    const ulonglong2* vnum2 = (const ulonglong2*)g_vnum;
    const float4* As4base = (const float4*)sm;

    for (int tt = blockIdx.x; tt < ntiles; tt += gridDim.x) {
        const int row0 = tt * TILE + 8 * w;

        // ---------------- embed + folded W_in (col-pair packed) ----------------
        u64 e0[8], e1[8];          // e0[r] = cols(4l,4l+1), e1[r] = cols(4l+2,4l+3)
#pragma unroll
        for (int r = 0; r < 8; r++) { e0[r] = bp0; e1[r] = bp1; }
        {
            const float* xr[8];
#pragma unroll
            for (int r = 0; r < 8; r++)
                xr[r] = x + (size_t)min(row0 + r, nrows - 1) * 40;
#pragma unroll
            for (int f = 0; f < NCAT; f++) {
                int base = f * NMOD;
#pragma unroll
                for (int r = 0; r < 8; r++) {
                    ulonglong2 tp = Tcat2[((base + (int)xr[r][f]) << 5) + l];
                    e0[r] = add2(e0[r], tp.x);
                    e1[r] = add2(e1[r], tp.y);
                }
            }
#pragma unroll
            for (int f = 0; f < NNUM; f++) {
                ulonglong2 vp = vnum2[(f << 5) + l];
#pragma unroll
                for (int r = 0; r < 8; r++) {
                    u64 d = dup2(xr[r][NCAT + f]);
                    e0[r] = fma2(vp.x, d, e0[r]);
                    e1[r] = fma2(vp.y, d, e1[r]);
                }
            }
        }
        // transpose-store h1 into htw: htw[swz(2k+p)], k = 4l+c
        {
            float ec[8][4];
#pragma unroll
            for (int r = 0; r < 8; r++) {
                float2 a = upk2(e0[r]), b = upk2(e1[r]);
                ec[r][0] = a.x; ec[r][1] = a.y; ec[r][2] = b.x; ec[r][3] = b.y;
            }
#pragma unroll
            for (int c = 0; c < 4; c++) {
                ulonglong2 v0, v1;
                v0.x = pk2(ec[0][c], ec[1][c]); v0.y = pk2(ec[2][c], ec[3][c]);
                v1.x = pk2(ec[4][c], ec[5][c]); v1.y = pk2(ec[6][c], ec[7][c]);
                htw[swz(2 * (4 * l + c) + 0)] = v0;
                htw[swz(2 * (4 * l + c) + 1)] = v1;
            }
        }
        __syncwarp();

        // ---------------- 3 GEMM stages (warp-local, f32x2) ----------------
        u64 acc[4][4];   // [rowpair 01/23/45/67][col]
#pragma unroll 1
        for (int s = 0; s < 3; s++) {
            {
                const float4 dj = (s == 0) ? dv0 : (s == 1) ? dv1 : dv2;
                u64 i0 = dup2(dj.x), i1 = dup2(dj.y), i2 = dup2(dj.z), i3 = dup2(dj.w);
#pragma unroll
                for (int rp = 0; rp < 4; rp++) {
                    acc[rp][0] = i0; acc[rp][1] = i1; acc[rp][2] = i2; acc[rp][3] = i3;
                }
            }
            const float4* As4 = As4base + s * (HID * HID / 4) + l;
#pragma unroll 4
            for (int k = 0; k < HID; k++) {
                float4 av = As4[k * 32];
                ulonglong2 hA = htw[swz(2 * k)];
                ulonglong2 hB = htw[swz(2 * k + 1)];
                u64 d0 = dup2(av.x), d1 = dup2(av.y), d2 = dup2(av.z), d3 = dup2(av.w);
                acc[0][0] = fma2(hA.x, d0, acc[0][0]);
                acc[1][0] = fma2(hA.y, d0, acc[1][0]);
                acc[2][0] = fma2(hB.x, d0, acc[2][0]);
                acc[3][0] = fma2(hB.y, d0, acc[3][0]);
                acc[0][1] = fma2(hA.x, d1, acc[0][1]);
                acc[1][1] = fma2(hA.y, d1, acc[1][1]);
                acc[2][1] = fma2(hB.x, d1, acc[2][1]);
                acc[3][1] = fma2(hB.y, d1, acc[3][1]);
                acc[0][2] = fma2(hA.x, d2, acc[0][2]);
                acc[1][2] = fma2(hA.y, d2, acc[1][2]);
                acc[2][2] = fma2(hB.x, d2, acc[2][2]);
                acc[3][2] = fma2(hB.y, d2, acc[3][2]);
                acc[0][3] = fma2(hA.x, d3, acc[0][3]);
                acc[1][3] = fma2(hA.y, d3, acc[1][3]);
                acc[2][3] = fma2(hB.x, d3, acc[2][3]);
                acc[3][3] = fma2(hB.y, d3, acc[3][3]);
            }

            if (s == 2) {
                // output: rows row0..row0+7, cols 4l..4l+3 (STG.128)
                float4* o4 = (float4*)out;
#pragma unroll
                for (int rp = 0; rp < 4; rp++) {
                    float2 c0 = upk2(acc[rp][0]), c1 = upk2(acc[rp][1]);
                    float2 c2 = upk2(acc[rp][2]), c3 = upk2(acc[rp][3]);
                    int ra = row0 + 2 * rp, rb = ra + 1;
                    if (ra < nrows)
                        o4[(size_t)ra * 32 + l] = make_float4(c0.x, c1.x, c2.x, c3.x);
                    if (rb < nrows)
                        o4[(size_t)rb * 32 + l] = make_float4(c0.y, c1.y, c2.y, c3.y);
                }
            } else {
                // ---- LayerNorm per row (packed row-pairs, warp shuffles) ----
#pragma unroll
                for (int rp = 0; rp < 4; rp++) {
                    u64 s1 = add2(add2(acc[rp][0], acc[rp][1]),
                                  add2(acc[rp][2], acc[rp][3]));
                    u64 s2 = fma2(acc[rp][0], acc[rp][0],
                             fma2(acc[rp][1], acc[rp][1],
                             fma2(acc[rp][2], acc[rp][2],
                             mul2(acc[rp][3], acc[rp][3]))));
#pragma unroll
                    for (int off = 16; off; off >>= 1) {
                        s1 = add2(s1, __shfl_xor_sync(0xffffffffu, s1, off));
                        s2 = add2(s2, __shfl_xor_sync(0xffffffffu, s2, off));
                    }
                    float2 m = upk2(mul2(s1, inv2));
                    float2 q = upk2(mul2(s2, inv2));
                    float r0 = rsqrtf(q.x - m.x * m.x + 1e-5f);
                    float r1 = rsqrtf(q.y - m.y * m.y + 1e-5f);
                    u64 rr  = pk2(r0, r1);
                    u64 nmr = pk2(-m.x * r0, -m.y * r1);
#pragma unroll
                    for (int c = 0; c < 4; c++)
                        acc[rp][c] = fma2(acc[rp][c], rr, nmr);
                }
                __syncwarp();   // reads of htw done before overwrite
#pragma unroll
                for (int c = 0; c < 4; c++) {
                    ulonglong2 v0, v1;
                    v0.x = acc[0][c]; v0.y = acc[1][c];
                    v1.x = acc[2][c]; v1.y = acc[3][c];
                    htw[swz(2 * (4 * l + c) + 0)] = v0;
                    htw[swz(2 * (4 * l + c) + 1)] = v1;
                }
                __syncwarp();
            }
        }
        __syncwarp();   // htw reads complete before next tile overwrites
    }
}

// ---------------- launch ----------------
extern "C" void kernel_launch(void* const* d_in, const int* in_sizes, int n_in,
                              void* d_out, int out_size) {
    const float* x     = (const float*)d_in[0];
    const float* emb   = (const float*)d_in[1];
    const float* W_num = (const float*)d_in[2];
    const float* b_num = (const float*)d_in[3];
    const float* W_in  = (const float*)d_in[4];
    const float* b_in  = (const float*)d_in[5];
    const float* W1    = (const float*)d_in[6];
    const float* b1    = (const float*)d_in[7];
    const float* W2    = (const float*)d_in[8];
    const float* b2    = (const float*)d_in[9];
    const float* ln_g  = (const float*)d_in[10];
    const float* ln_b  = (const float*)d_in[11];
    const float* W_out = (const float*)d_in[12];
    const float* b_out = (const float*)d_in[13];
    float* out = (float*)d_out;

    const int nrows  = in_sizes[0] / 40;
    const int ntiles = (nrows + TILE - 1) / TILE;
    const int smem_bytes = SM_TOTALF * (int)sizeof(float);   // 229376

    static int smem_set = 0;
    if (!smem_set) {
        cudaFuncSetAttribute(main_kernel, cudaFuncAttributeMaxDynamicSharedMemorySize,
                             smem_bytes);
        smem_set = 1;
    }

    pre_all_kernel<<<NCAT * NMOD + 3 * HID + 1, HID>>>(
        emb, W_num, b_num, W_in, b_in, W1, b1, W2, b2, ln_g, ln_b, W_out, b_out);
    main_kernel<<<148, NTHR, smem_bytes>>>(x, out, nrows, ntiles);
}

// round 6
// speedup vs baseline: 1.0230x; 1.0230x over previous
#include <cuda_runtime.h>

#define NCAT 20
#define NNUM 20
#define EMBD 32
#define HID  128
#define NMOD 50
#define TILE 64            // 16 warps * 4 rows
#define NTHR 512

typedef unsigned long long u64;

// ---------------- f32x2 helpers ----------------
__device__ __forceinline__ u64 pk2(float lo, float hi) {
    u64 r; asm("mov.b64 %0,{%1,%2};" : "=l"(r) : "f"(lo), "f"(hi)); return r;
}
__device__ __forceinline__ float2 upk2(u64 v) {
    float2 f; asm("mov.b64 {%0,%1},%2;" : "=f"(f.x), "=f"(f.y) : "l"(v)); return f;
}
__device__ __forceinline__ u64 dup2(float a) {
    u64 r; asm("mov.b64 %0,{%1,%1};" : "=l"(r) : "f"(a)); return r;
}
__device__ __forceinline__ u64 fma2(u64 a, u64 b, u64 c) {
    u64 d; asm("fma.rn.f32x2 %0,%1,%2,%3;" : "=l"(d) : "l"(a), "l"(b), "l"(c)); return d;
}
__device__ __forceinline__ u64 add2(u64 a, u64 b) {
    u64 d; asm("add.rn.f32x2 %0,%1,%2;" : "=l"(d) : "l"(a), "l"(b)); return d;
}
__device__ __forceinline__ u64 mul2(u64 a, u64 b) {
    u64 d; asm("mul.rn.f32x2 %0,%1,%2;" : "=l"(d) : "l"(a), "l"(b)); return d;
}
// u2-index swizzle (16B units) for conflict-free transposed stores
__device__ __forceinline__ int swz(int i) { return i ^ ((i >> 3) & 7); }

// ---------------- device scratch ----------------
__device__ float g_Tcat[NCAT * NMOD * HID];
__device__ float g_A[3 * HID * HID];
__device__ float g_vnum[NNUM * HID];
__device__ float g_base[HID];
__device__ float g_d[3 * HID];

// ---------------- merged precompute kernel ----------------
__global__ void pre_all_kernel(const float* __restrict__ emb,
                               const float* __restrict__ W_num, const float* __restrict__ b_num,
                               const float* __restrict__ W_in,  const float* __restrict__ b_in,
                               const float* __restrict__ W1,    const float* __restrict__ b1,
                               const float* __restrict__ W2,    const float* __restrict__ b2,
                               const float* __restrict__ ln_g,  const float* __restrict__ ln_b,
                               const float* __restrict__ W_out, const float* __restrict__ b_out) {
    const int b = blockIdx.x;
    const int j = threadIdx.x;
    if (b < NCAT * NMOD) {
        int fc = b, f = fc / NMOD;
        const float* e = emb + fc * EMBD;
        float s = 0.f;
#pragma unroll
        for (int k = 0; k < EMBD; k++)
            s += e[k] * W_in[(f * EMBD + k) * HID + j];
        g_Tcat[fc * HID + j] = s;
    } else if (b < NCAT * NMOD + 3 * HID) {
        int bx = b - NCAT * NMOD;
        int s = bx >> 7, k = bx & 127;
        float v;
        if (s == 2) {
            v = ln_g[HID + k] * W_out[k * HID + j];
        } else {
            const float* w1 = W1 + s * HID * 2 * HID + k * 2 * HID;
            const float* w2 = W2 + s * 2 * HID * HID;
            float acc = 0.f;
            for (int m = 0; m < 2 * HID; m++) acc += w1[m] * w2[m * HID + j];
            v = (s == 1) ? ln_g[k] * acc : acc;
        }
        g_A[bx * HID + j] = v;
    } else {
        for (int f = 0; f < NNUM; f++) {
            float s = 0.f;
#pragma unroll
            for (int k = 0; k < EMBD; k++)
                s += W_num[f * EMBD + k] * W_in[((NCAT + f) * EMBD + k) * HID + j];
            g_vnum[f * HID + j] = s;
        }
        float bb = b_in[j];
        for (int f = 0; f < NNUM; f++)
#pragma unroll
            for (int k = 0; k < EMBD; k++)
                bb += b_num[f * EMBD + k] * W_in[((NCAT + f) * EMBD + k) * HID + j];
        g_base[j] = bb;
        float d1 = b2[j];
        for (int m = 0; m < 2 * HID; m++) d1 += b1[m] * W2[m * HID + j];
        g_d[j] = d1;
        __shared__ float u[2 * HID];
        for (int m = j; m < 2 * HID; m += HID) {
            float s = 0.f;
            for (int k = 0; k < HID; k++)
                s += ln_b[k] * W1[HID * 2 * HID + k * 2 * HID + m];
            u[m] = s;
        }
        __syncthreads();
        float d2 = b2[HID + j];
        for (int m = 0; m < 2 * HID; m++)
            d2 += (u[m] + b1[2 * HID + m]) * W2[2 * HID * HID + m * HID + j];
        g_d[HID + j] = d2;
        float d3 = b_out[j];
        for (int k = 0; k < HID; k++) d3 += ln_b[HID + k] * W_out[k * HID + j];
        g_d[2 * HID + j] = d3;
    }
}

// ---------------- main fused kernel ----------------
// smem: A (3*128*128 fp32 = 192KB) + per-warp htw (128 ulonglong2, swizzled) = 2KB*16
#define SM_HT     (3 * HID * HID)                 // float offset 49152
#define SM_TOTALF (SM_HT + 16 * HID * 4)          // + 8192 floats -> 229376 B

__global__ __launch_bounds__(NTHR, 1)
void main_kernel(const float* __restrict__ x, float* __restrict__ out,
                 int nrows, int ntiles) {
    extern __shared__ float sm[];
    const int t = threadIdx.x;
    const int l = t & 31;          // lane: cols 4l..4l+3
    const int w = t >> 5;          // warp: rows 4w..4w+3 of tile

    ulonglong2* htw = (ulonglong2*)(sm + SM_HT) + w * HID;   // 128 u2 per warp

    // load folded matrices once per CTA
    {
        const float4* src = (const float4*)g_A;
        float4* dst = (float4*)sm;
        for (int i = t; i < 3 * HID * HID / 4; i += NTHR) dst[i] = src[i];
    }

    // per-thread constants
    const float4 bj  = ((const float4*)g_base)[l];
    const float4 dv0 = ((const float4*)g_d)[l];
    const float4 dv1 = ((const float4*)g_d)[32 + l];
    const float4 dv2 = ((const float4*)g_d)[64 + l];
    const u64 inv2 = dup2(1.f / HID);

    __syncthreads();   // only CTA-wide barrier

    const float4* Tcat4 = (const float4*)g_Tcat;
    const float4* vnum4 = (const float4*)g_vnum;
    const float4* As4base = (const float4*)sm;

    for (int tt = blockIdx.x; tt < ntiles; tt += gridDim.x) {
        const int row0 = tt * TILE + 4 * w;

        // ---------------- embed + folded W_in : rows row0..row0+3, cols 4l..4l+3
        float4 a0 = bj, a1 = bj, a2 = bj, a3 = bj;
        {
            const float* x0 = x + (size_t)min(row0 + 0, nrows - 1) * 40;
            const float* x1 = x + (size_t)min(row0 + 1, nrows - 1) * 40;
            const float* x2 = x + (size_t)min(row0 + 2, nrows - 1) * 40;
            const float* x3 = x + (size_t)min(row0 + 3, nrows - 1) * 40;
#pragma unroll
            for (int f = 0; f < NCAT; f++) {
                int base = f * NMOD;
                float4 t0 = Tcat4[((base + (int)x0[f]) << 5) + l];
                float4 t1 = Tcat4[((base + (int)x1[f]) << 5) + l];
                float4 t2 = Tcat4[((base + (int)x2[f]) << 5) + l];
                float4 t3 = Tcat4[((base + (int)x3[f]) << 5) + l];
                a0.x += t0.x; a0.y += t0.y; a0.z += t0.z; a0.w += t0.w;
                a1.x += t1.x; a1.y += t1.y; a1.z += t1.z; a1.w += t1.w;
                a2.x += t2.x; a2.y += t2.y; a2.z += t2.z; a2.w += t2.w;
                a3.x += t3.x; a3.y += t3.y; a3.z += t3.z; a3.w += t3.w;
            }
#pragma unroll
            for (int f = 0; f < NNUM; f++) {
                float4 v = vnum4[(f << 5) + l];
                float s0 = x0[NCAT + f], s1 = x1[NCAT + f];
                float s2 = x2[NCAT + f], s3 = x3[NCAT + f];
                a0.x += s0 * v.x; a0.y += s0 * v.y; a0.z += s0 * v.z; a0.w += s0 * v.w;
                a1.x += s1 * v.x; a1.y += s1 * v.y; a1.z += s1 * v.z; a1.w += s1 * v.w;
                a2.x += s2 * v.x; a2.y += s2 * v.y; a2.z += s2 * v.z; a2.w += s2 * v.w;
                a3.x += s3 * v.x; a3.y += s3 * v.y; a3.z += s3 * v.z; a3.w += s3 * v.w;
            }
        }
        // transpose-store h1: htw[swz(4l+c)] = {pk(r0,r1), pk(r2,r3)} for col c
        {
            ulonglong2 v;
            v.x = pk2(a0.x, a1.x); v.y = pk2(a2.x, a3.x); htw[swz(4 * l + 0)] = v;
            v.x = pk2(a0.y, a1.y); v.y = pk2(a2.y, a3.y); htw[swz(4 * l + 1)] = v;
            v.x = pk2(a0.z, a1.z); v.y = pk2(a2.z, a3.z); htw[swz(4 * l + 2)] = v;
            v.x = pk2(a0.w, a1.w); v.y = pk2(a2.w, a3.w); htw[swz(4 * l + 3)] = v;
        }
        __syncwarp();

        // ---------------- 3 GEMM stages (warp-local, f32x2) ----------------
        u64 acc[2][4];   // [rowpair 01 / 23][col]
#pragma unroll 1
        for (int s = 0; s < 3; s++) {
            {
                const float4 dj = (s == 0) ? dv0 : (s == 1) ? dv1 : dv2;
                acc[0][0] = dup2(dj.x); acc[0][1] = dup2(dj.y);
                acc[0][2] = dup2(dj.z); acc[0][3] = dup2(dj.w);
                acc[1][0] = acc[0][0];  acc[1][1] = acc[0][1];
                acc[1][2] = acc[0][2];  acc[1][3] = acc[0][3];
            }
            const float4* As4 = As4base + s * (HID * HID / 4) + l;
#pragma unroll 8
            for (int k = 0; k < HID; k++) {
                float4 av = As4[k * 32];
                ulonglong2 hv = htw[swz(k)];
                u64 d0 = dup2(av.x), d1 = dup2(av.y), d2 = dup2(av.z), d3 = dup2(av.w);
                acc[0][0] = fma2(hv.x, d0, acc[0][0]);
                acc[1][0] = fma2(hv.y, d0, acc[1][0]);
                acc[0][1] = fma2(hv.x, d1, acc[0][1]);
                acc[1][1] = fma2(hv.y, d1, acc[1][1]);
                acc[0][2] = fma2(hv.x, d2, acc[0][2]);
                acc[1][2] = fma2(hv.y, d2, acc[1][2]);
                acc[0][3] = fma2(hv.x, d3, acc[0][3]);
                acc[1][3] = fma2(hv.y, d3, acc[1][3]);
            }

            if (s == 2) {
                // output rows row0..row0+3, cols 4l..4l+3 (STG.128)
                float4* o4 = (float4*)out;
#pragma unroll
                for (int rp = 0; rp < 2; rp++) {
                    float2 c0 = upk2(acc[rp][0]), c1 = upk2(acc[rp][1]);
                    float2 c2 = upk2(acc[rp][2]), c3 = upk2(acc[rp][3]);
                    int ra = row0 + 2 * rp, rb = ra + 1;
                    if (ra < nrows)
                        o4[(size_t)ra * 32 + l] = make_float4(c0.x, c1.x, c2.x, c3.x);
                    if (rb < nrows)
                        o4[(size_t)rb * 32 + l] = make_float4(c0.y, c1.y, c2.y, c3.y);
                }
            } else {
                // ---- LayerNorm per row (packed row-pairs, warp shuffles) ----
#pragma unroll
                for (int rp = 0; rp < 2; rp++) {
                    u64 s1 = add2(add2(acc[rp][0], acc[rp][1]),
                                  add2(acc[rp][2], acc[rp][3]));
                    u64 s2 = fma2(acc[rp][0], acc[rp][0],
                             fma2(acc[rp][1], acc[rp][1],
                             fma2(acc[rp][2], acc[rp][2],
                             mul2(acc[rp][3], acc[rp][3]))));
#pragma unroll
                    for (int off = 16; off; off >>= 1) {
                        s1 = add2(s1, __shfl_xor_sync(0xffffffffu, s1, off));
                        s2 = add2(s2, __shfl_xor_sync(0xffffffffu, s2, off));
                    }
                    float2 m = upk2(mul2(s1, inv2));
                    float2 q = upk2(mul2(s2, inv2));
                    float r0 = rsqrtf(q.x - m.x * m.x + 1e-5f);
                    float r1 = rsqrtf(q.y - m.y * m.y + 1e-5f);
                    u64 rr  = pk2(r0, r1);
                    u64 nmr = pk2(-m.x * r0, -m.y * r1);
#pragma unroll
                    for (int c = 0; c < 4; c++)
                        acc[rp][c] = fma2(acc[rp][c], rr, nmr);
                }
                __syncwarp();   // reads of htw done before overwrite
                {
                    ulonglong2 v;
                    v.x = acc[0][0]; v.y = acc[1][0]; htw[swz(4 * l + 0)] = v;
                    v.x = acc[0][1]; v.y = acc[1][1]; htw[swz(4 * l + 1)] = v;
                    v.x = acc[0][2]; v.y = acc[1][2]; htw[swz(4 * l + 2)] = v;
                    v.x = acc[0][3]; v.y = acc[1][3]; htw[swz(4 * l + 3)] = v;
                }
                __syncwarp();
            }
        }
        __syncwarp();   // htw reads complete before next tile overwrites
    }
}

// ---------------- launch ----------------
extern "C" void kernel_launch(void* const* d_in, const int* in_sizes, int n_in,
                              void* d_out, int out_size) {
    const float* x     = (const float*)d_in[0];
    const float* emb   = (const float*)d_in[1];
    const float* W_num = (const float*)d_in[2];
    const float* b_num = (const float*)d_in[3];
    const float* W_in  = (const float*)d_in[4];
    const float* b_in  = (const float*)d_in[5];
    const float* W1    = (const float*)d_in[6];
    const float* b1    = (const float*)d_in[7];
    const float* W2    = (const float*)d_in[8];
    const float* b2    = (const float*)d_in[9];
    const float* ln_g  = (const float*)d_in[10];
    const float* ln_b  = (const float*)d_in[11];
    const float* W_out = (const float*)d_in[12];
    const float* b_out = (const float*)d_in[13];
    float* out = (float*)d_out;

    const int nrows  = in_sizes[0] / 40;
    const int ntiles = (nrows + TILE - 1) / TILE;
    const int smem_bytes = SM_TOTALF * (int)sizeof(float);   // 229376

    static int smem_set = 0;
    if (!smem_set) {
        cudaFuncSetAttribute(main_kernel, cudaFuncAttributeMaxDynamicSharedMemorySize,
                             smem_bytes);
        smem_set = 1;
    }

    pre_all_kernel<<<NCAT * NMOD + 3 * HID + 1, HID>>>(
        emb, W_num, b_num, W_in, b_in, W1, b1, W2, b2, ln_g, ln_b, W_out, b_out);
    main_kernel<<<148, NTHR, smem_bytes>>>(x, out, nrows, ntiles);
}

// round 8
// speedup vs baseline: 1.3608x; 1.3303x over previous
#include <cuda_runtime.h>
#include <cuda_bf16.h>
#include <cstdint>

#define NCAT 20
#define NNUM 20
#define EMBD 32
#define HID  128
#define NMOD 50
#define NTHR 256

typedef unsigned long long u64;
typedef unsigned int u32;

// ---------------- smem layout ----------------
#define BSTR  136                       // bf16 per BT row (272 B): 68 u32 -> bank 4q+m, conflict-free
#define SSTR  140                       // f32 per staging row (560 B): 140 mod 32 = 12, conflict-free frag reads
#define OB    0                         // 6 * 128 * 272 = 208896 B (BT: s0hi,s0lo,s1hi,s1lo,s2hi,s2lo)
#define OST   208896                    // staging 32 * 560 = 17920 B
#define OD    226816                    // 384 * 4 = 1536 B bias vectors
#define SMEM_REQ 228448

// ---------------- device scratch ----------------
__device__ float g_Tcat[NCAT * NMOD * HID];
__device__ float g_vnum[NNUM * HID];
__device__ float g_base[HID];
__device__ float g_d[3 * HID];
__device__ __align__(16) unsigned short g_B[6 * HID * BSTR];   // BT[n][k], padded rows

// ---------------- helpers ----------------
__device__ __forceinline__ u64 dup2(float a) {
    u64 r; asm("mov.b64 %0,{%1,%1};" : "=l"(r) : "f"(a)); return r;
}
__device__ __forceinline__ float2 upk2(u64 v) {
    float2 f; asm("mov.b64 {%0,%1},%2;" : "=f"(f.x), "=f"(f.y) : "l"(v)); return f;
}
__device__ __forceinline__ u64 fma2(u64 a, u64 b, u64 c) {
    u64 d; asm("fma.rn.f32x2 %0,%1,%2,%3;" : "=l"(d) : "l"(a), "l"(b), "l"(c)); return d;
}
__device__ __forceinline__ u64 add2(u64 a, u64 b) {
    u64 d; asm("add.rn.f32x2 %0,%1,%2;" : "=l"(d) : "l"(a), "l"(b)); return d;
}
__device__ __forceinline__ u32 cvt_bf2(float hi_val, float lo_val) {  // word {hi=bf16(hi_val), lo=bf16(lo_val)}
    u32 w; asm("cvt.rn.bf16x2.f32 %0,%1,%2;" : "=r"(w) : "f"(hi_val), "f"(lo_val)); return w;
}
// split two f32 (c0 -> low half, c1 -> high half) into hi/lo bf16x2 words
__device__ __forceinline__ void split2(float c0, float c1, u32& hi, u32& lo) {
    hi = cvt_bf2(c1, c0);
    float e0 = c0 - __uint_as_float(hi << 16);
    float e1 = c1 - __uint_as_float(hi & 0xffff0000u);
    lo = cvt_bf2(e1, e0);
}

#define MMA(d, a, b0v, b1v) \
    asm volatile("mma.sync.aligned.m16n8k16.row.col.f32.bf16.bf16.f32 " \
        "{%0,%1,%2,%3},{%4,%5,%6,%7},{%8,%9},{%0,%1,%2,%3};" \
        : "+f"((d)[0]), "+f"((d)[1]), "+f"((d)[2]), "+f"((d)[3]) \
        : "r"((a)[0]), "r"((a)[1]), "r"((a)[2]), "r"((a)[3]), "r"(b0v), "r"(b1v))

// ---------------- precompute kernel ----------------
__global__ void pre_all_kernel(const float* __restrict__ emb,
                               const float* __restrict__ W_num, const float* __restrict__ b_num,
                               const float* __restrict__ W_in,  const float* __restrict__ b_in,
                               const float* __restrict__ W1,    const float* __restrict__ b1,
                               const float* __restrict__ W2,    const float* __restrict__ b2,
                               const float* __restrict__ ln_g,  const float* __restrict__ ln_b,
                               const float* __restrict__ W_out, const float* __restrict__ b_out) {
    const int b = blockIdx.x;
    const int j = threadIdx.x;
    if (b < NCAT * NMOD) {
        int fc = b, f = fc / NMOD;
        const float* e = emb + fc * EMBD;
        float s = 0.f;
#pragma unroll
        for (int k = 0; k < EMBD; k++) s += e[k] * W_in[(f * EMBD + k) * HID + j];
        g_Tcat[fc * HID + j] = s;
    } else if (b < NCAT * NMOD + 3 * HID) {
        int bx = b - NCAT * NMOD;
        int s = bx >> 7, k = bx & 127;
        float v;
        if (s == 2) {
            v = ln_g[HID + k] * W_out[k * HID + j];
        } else {
            const float* w1 = W1 + s * HID * 2 * HID + k * 2 * HID;
            const float* w2 = W2 + s * 2 * HID * HID;
            float acc = 0.f;
            for (int m = 0; m < 2 * HID; m++) acc += w1[m] * w2[m * HID + j];
            v = (s == 1) ? ln_g[k] * acc : acc;
        }
        // BT[n=j][k] = A_s[k][j]; hi/lo bf16
        __nv_bfloat16 h = __float2bfloat16(v);
        float rem = v - __bfloat162float(h);
        __nv_bfloat16 lo = __float2bfloat16(rem);
        g_B[(size_t)(s * 2 + 0) * HID * BSTR + j * BSTR + k] = *reinterpret_cast<unsigned short*>(&h);
        g_B[(size_t)(s * 2 + 1) * HID * BSTR + j * BSTR + k] = *reinterpret_cast<unsigned short*>(&lo);
    } else {
        for (int f = 0; f < NNUM; f++) {
            float s = 0.f;
#pragma unroll
            for (int k = 0; k < EMBD; k++)
                s += W_num[f * EMBD + k] * W_in[((NCAT + f) * EMBD + k) * HID + j];
            g_vnum[f * HID + j] = s;
        }
        float bb = b_in[j];
        for (int f = 0; f < NNUM; f++)
#pragma unroll
            for (int k = 0; k < EMBD; k++)
                bb += b_num[f * EMBD + k] * W_in[((NCAT + f) * EMBD + k) * HID + j];
        g_base[j] = bb;
        float d1 = b2[j];
        for (int m = 0; m < 2 * HID; m++) d1 += b1[m] * W2[m * HID + j];
        g_d[j] = d1;
        __shared__ float u[2 * HID];
        for (int m = j; m < 2 * HID; m += HID) {
            float s = 0.f;
            for (int k = 0; k < HID; k++)
                s += ln_b[k] * W1[HID * 2 * HID + k * 2 * HID + m];
            u[m] = s;
        }
        __syncthreads();
        float d2 = b2[HID + j];
        for (int m = 0; m < 2 * HID; m++)
            d2 += (u[m] + b1[2 * HID + m]) * W2[2 * HID * HID + m * HID + j];
        g_d[HID + j] = d2;
        float d3 = b_out[j];
        for (int k = 0; k < HID; k++) d3 += ln_b[HID + k] * W_out[k * HID + j];
        g_d[2 * HID + j] = d3;
    }
}

// ---------------- main fused kernel ----------------
__global__ __launch_bounds__(NTHR, 1)
void main_kernel(const float* __restrict__ x, float* __restrict__ out,
                 int nrows, int ntiles) {
    extern __shared__ __align__(16) char smem[];
    const int t = threadIdx.x;
    const int w = t >> 5;
    const int l = t & 31;
    const int q = l >> 2;      // lane/4 : row offset (D/A) & B n-offset
    const int m = l & 3;       // lane%4 : col-pair index

    // copy BT matrices (208896 B) and bias vectors
    {
        const float4* src = (const float4*)g_B;
        float4* dst = (float4*)(smem + OB);
        for (int i = t; i < 208896 / 16; i += NTHR) dst[i] = src[i];
        float* dd = (float*)(smem + OD);
        for (int i = t; i < 3 * HID; i += NTHR) dd[i] = g_d[i];
    }
    __syncthreads();

    const unsigned short* BT = (const unsigned short*)(smem + OB);
    float* stg = (float*)(smem + OST);
    const float* dsm = (const float*)(smem + OD);

    const u64* Tc = (const u64*)g_Tcat;
    const u64* Vn = (const u64*)g_vnum;
    const u64* Bs = (const u64*)g_base;
    const int p  = t & 63;     // embed: col pair 2p,2p+1
    const int rg = t >> 6;     // embed: row octet within 32-row chunk

    for (int tt = blockIdx.x; tt < ntiles; tt += gridDim.x) {
        const int row0 = tt * 128;

        // ============ embed 4 chunks of 32 rows -> staging -> A fragments ============
        u32 AH[8][4], AL[8][4];
        for (int c = 0; c < 4; c++) {
            const int crow = row0 + 32 * c;
            {
                u64 vn[NNUM];
#pragma unroll
                for (int f = 0; f < NNUM; f++) vn[f] = __ldg(Vn + f * 64 + p);
                u64 bb = __ldg(Bs + p);
#pragma unroll 2
                for (int i = 0; i < 8; i++) {
                    int r = rg * 8 + i;
                    const float* xr = x + (size_t)min(crow + r, nrows - 1) * 40;
                    u64 acc = bb;
#pragma unroll
                    for (int f = 0; f < NCAT; f++) {
                        int idx = (int)xr[f];
                        acc = add2(acc, __ldg(Tc + (f * NMOD + idx) * 64 + p));
                    }
#pragma unroll
                    for (int f = 0; f < NNUM; f++)
                        acc = fma2(vn[f], dup2(xr[NCAT + f]), acc);
                    float2 v = upk2(acc);
                    *(float2*)&stg[r * SSTR + 2 * p] = v;
                }
            }
            __syncthreads();
            if ((w >> 1) == c) {
                const int rb = (w & 1) * 16 + q;   // row within chunk (and +8)
#pragma unroll
                for (int kt = 0; kt < 8; kt++) {
                    int c0 = 16 * kt + 2 * m;
                    float2 v00 = *(const float2*)&stg[rb * SSTR + c0];
                    float2 v10 = *(const float2*)&stg[(rb + 8) * SSTR + c0];
                    float2 v01 = *(const float2*)&stg[rb * SSTR + c0 + 8];
                    float2 v11 = *(const float2*)&stg[(rb + 8) * SSTR + c0 + 8];
                    split2(v00.x, v00.y, AH[kt][0], AL[kt][0]);
                    split2(v10.x, v10.y, AH[kt][1], AL[kt][1]);
                    split2(v01.x, v01.y, AH[kt][2], AL[kt][2]);
                    split2(v11.x, v11.y, AH[kt][3], AL[kt][3]);
                }
            }
            __syncthreads();
        }

        // ============ 3 MMA stages, all warp-local ============
        float D[16][4];
#pragma unroll 1
        for (int s = 0; s < 3; s++) {
            // bias init
#pragma unroll
            for (int nt = 0; nt < 16; nt++) {
                float2 bv = *(const float2*)&dsm[s * HID + nt * 8 + 2 * m];
                D[nt][0] = bv.x; D[nt][1] = bv.y; D[nt][2] = bv.x; D[nt][3] = bv.y;
            }
            const unsigned short* B0 = BT + (size_t)(s * 2) * HID * BSTR;
            const unsigned short* B1 = B0 + (size_t)HID * BSTR;
#pragma unroll
            for (int kt = 0; kt < 8; kt++) {
                const int koff = kt * 16 + 2 * m;
#pragma unroll
                for (int nt = 0; nt < 16; nt++) {
                    const u32* pb = (const u32*)(B0 + (nt * 8 + q) * BSTR + koff);
                    u32 b0 = pb[0], b1 = pb[4];
                    MMA(D[nt], AH[kt], b0, b1);
                    MMA(D[nt], AL[kt], b0, b1);
                }
#pragma unroll
                for (int nt = 0; nt < 16; nt++) {
                    const u32* pb = (const u32*)(B1 + (nt * 8 + q) * BSTR + koff);
                    u32 b0 = pb[0], b1 = pb[4];
                    MMA(D[nt], AH[kt], b0, b1);
                }
            }

            if (s < 2) {
                // ---- LayerNorm (rows g=q and q+8): reduce across 4-lane m-group ----
                float s1a = 0.f, s2a = 0.f, s1b = 0.f, s2b = 0.f;
#pragma unroll
                for (int nt = 0; nt < 16; nt++) {
                    s1a += D[nt][0] + D[nt][1];
                    s2a += D[nt][0] * D[nt][0] + D[nt][1] * D[nt][1];
                    s1b += D[nt][2] + D[nt][3];
                    s2b += D[nt][2] * D[nt][2] + D[nt][3] * D[nt][3];
                }
#pragma unroll
                for (int off = 1; off <= 2; off <<= 1) {
                    s1a += __shfl_xor_sync(0xffffffffu, s1a, off);
                    s2a += __shfl_xor_sync(0xffffffffu, s2a, off);
                    s1b += __shfl_xor_sync(0xffffffffu, s1b, off);
                    s2b += __shfl_xor_sync(0xffffffffu, s2b, off);
                }
                const float inv = 1.f / HID;
                float mua = s1a * inv, mub = s1b * inv;
                float rsa = rsqrtf(s2a * inv - mua * mua + 1e-5f);
                float rsb = rsqrtf(s2b * inv - mub * mub + 1e-5f);
                float nma = -mua * rsa, nmb = -mub * rsb;
                // ---- D -> next-stage A fragments (register-only) ----
#pragma unroll
                for (int kt = 0; kt < 8; kt++) {
                    int n0 = 2 * kt, n1 = 2 * kt + 1;
                    split2(D[n0][0] * rsa + nma, D[n0][1] * rsa + nma, AH[kt][0], AL[kt][0]);
                    split2(D[n0][2] * rsb + nmb, D[n0][3] * rsb + nmb, AH[kt][1], AL[kt][1]);
                    split2(D[n1][0] * rsa + nma, D[n1][1] * rsa + nma, AH[kt][2], AL[kt][2]);
                    split2(D[n1][2] * rsb + nmb, D[n1][3] * rsb + nmb, AH[kt][3], AL[kt][3]);
                }
            } else {
                // ---- final store ----
                int ra = row0 + 16 * w + q;
                int rb2 = ra + 8;
#pragma unroll
                for (int nt = 0; nt < 16; nt++) {
                    int col = nt * 8 + 2 * m;
                    if (ra < nrows)
                        *(float2*)&out[(size_t)ra * HID + col] = make_float2(D[nt][0], D[nt][1]);
                    if (rb2 < nrows)
                        *(float2*)&out[(size_t)rb2 * HID + col] = make_float2(D[nt][2], D[nt][3]);
                }
            }
        }
    }
}

// ---------------- launch ----------------
extern "C" void kernel_launch(void* const* d_in, const int* in_sizes, int n_in,
                              void* d_out, int out_size) {
    const float* x     = (const float*)d_in[0];
    const float* emb   = (const float*)d_in[1];
    const float* W_num = (const float*)d_in[2];
    const float* b_num = (const float*)d_in[3];
    const float* W_in  = (const float*)d_in[4];
    const float* b_in  = (const float*)d_in[5];
    const float* W1    = (const float*)d_in[6];
    const float* b1    = (const float*)d_in[7];
    const float* W2    = (const float*)d_in[8];
    const float* b2    = (const float*)d_in[9];
    const float* ln_g  = (const float*)d_in[10];
    const float* ln_b  = (const float*)d_in[11];
    const float* W_out = (const float*)d_in[12];
    const float* b_out = (const float*)d_in[13];
    float* out = (float*)d_out;

    const int nrows  = in_sizes[0] / 40;
    const int ntiles = (nrows + 127) / 128;

    static int smem_set = 0;
    if (!smem_set) {
        cudaFuncSetAttribute(main_kernel, cudaFuncAttributeMaxDynamicSharedMemorySize,
                             SMEM_REQ);
        smem_set = 1;
    }

    pre_all_kernel<<<NCAT * NMOD + 3 * HID + 1, HID>>>(
        emb, W_num, b_num, W_in, b_in, W1, b1, W2, b2, ln_g, ln_b, W_out, b_out);
    main_kernel<<<148, NTHR, SMEM_REQ>>>(x, out, nrows, ntiles);
}